// round 7
// baseline (speedup 1.0000x reference)
#include <cuda_runtime.h>
#include <cuda_fp16.h>

// Problem constants
#define NN    50000
#define EE    800000
#define ROW   160     // logical node-prep row in floats: [T 0..127 | xb 128..143 | rootx 144..159]
#define ROWH  192     // fp16 storage row stride in halves = 384 B = 3 x 128B lines
                      // line0: T d0..3 (halves 0..63), line1: T d4..7 (64..127), line2: xb (128..143)+pad

// ---------------- scratch (static device memory; no runtime allocation) ----------------
__device__ __half g_TextH[(size_t)NN * ROWH];   // 19.2 MB, fits L2
__device__ float  g_rootx[NN * 16];
__device__ float  g_h[NN * 16];
__device__ float  g_agg0[NN * 16];
__device__ float  g_agg1[NN * 16];
__device__ float  g_cnt[NN];
__device__ int    g_is64;   // 1 if edge_index is int64, 0 if int32

// ---------------- helpers ----------------
__device__ __forceinline__ float4 f4fma(float s, float4 a, float4 b) {
    b.x = fmaf(s, a.x, b.x);
    b.y = fmaf(s, a.y, b.y);
    b.z = fmaf(s, a.z, b.z);
    b.w = fmaf(s, a.w, b.w);
    return b;
}

// vectorized no-return atomic add (sm_90+, PTX ISA 8.1)
__device__ __forceinline__ void red4(float* p, float4 v) {
    asm volatile("red.global.add.v4.f32 [%0], {%1, %2, %3, %4};"
                 :: "l"(p), "f"(v.x), "f"(v.y), "f"(v.z), "f"(v.w)
                 : "memory");
}

// ---------------- kernels ----------------

// Probe edge_index dtype: int64 vs JAX-x64-disabled int32. Parallel (1 warp).
__global__ void detect_kernel(const void* ei) {
    const unsigned long long* p = (const unsigned long long*)ei;
    int t = threadIdx.x;
    bool bad = (p[t] >= (unsigned long long)NN) ||
               (p[t + 32] >= (unsigned long long)NN);
    unsigned m = __ballot_sync(0xffffffffu, bad);
    if (t == 0) g_is64 = (m == 0) ? 1 : 0;
}

__global__ void zero_kernel() {
    int idx = blockIdx.x * blockDim.x + threadIdx.x;
    int stride = gridDim.x * blockDim.x;
    for (int i = idx; i < NN * 16; i += stride) {
        g_agg0[i] = 0.f;
        g_agg1[i] = 0.f;
    }
    for (int i = idx; i < NN; i += stride) g_cnt[i] = 0.f;
}

// Build per-node tables:
//   j in [0,128):   T[n,d,o]   = sum_i in[n,i] * nn_w[d*256+i*16+o]  -> fp16 g_TextH halves [0,128)
//   j in [128,144): xb[n,o]    = sum_i in[n,i] * nn_b[i*16+o]        -> fp16 g_TextH halves [128,144)
//   j in [144,160): rootx[n,o] = sum_i in[n,i] * root[i*16+o]+bias[o]-> fp32 g_rootx
__global__ void node_prep_kernel(const float* __restrict__ xin,   // nullptr -> use g_h
                                 const float* __restrict__ nw,
                                 const float* __restrict__ nb,
                                 const float* __restrict__ rt,
                                 const float* __restrict__ bs) {
    __shared__ float Wc[16 * ROW];
    __shared__ float Bc[ROW];
    const float* in = (xin != nullptr) ? xin : g_h;

    for (int t = threadIdx.x; t < 16 * ROW; t += blockDim.x) {
        int i = t / ROW, j = t % ROW;
        float w;
        if (j < 128) {
            int d = j >> 4, o = j & 15;
            w = nw[d * 256 + i * 16 + o];
        } else if (j < 144) {
            int o = j - 128;
            w = nb[i * 16 + o];
        } else {
            int o = j - 144;
            w = rt[i * 16 + o];
        }
        Wc[t] = w;
    }
    for (int t = threadIdx.x; t < ROW; t += blockDim.x)
        Bc[t] = (t >= 144) ? bs[t - 144] : 0.f;
    __syncthreads();

    const int total = NN * (ROW / 4);  // one thread per float4 of logical output
    for (int g = blockIdx.x * blockDim.x + threadIdx.x; g < total;
         g += gridDim.x * blockDim.x) {
        int n = g / (ROW / 4);
        int j4 = g % (ROW / 4);
        const float4* xr = (const float4*)(in + (size_t)n * 16);
        float4 x0 = xr[0], x1 = xr[1], x2 = xr[2], x3 = xr[3];
        float xv[16] = {x0.x, x0.y, x0.z, x0.w, x1.x, x1.y, x1.z, x1.w,
                        x2.x, x2.y, x2.z, x2.w, x3.x, x3.y, x3.z, x3.w};
        float4 acc = *(const float4*)&Bc[j4 * 4];
#pragma unroll
        for (int i = 0; i < 16; i++) {
            float4 w = *(const float4*)&Wc[i * ROW + j4 * 4];
            acc = f4fma(xv[i], w, acc);
        }
        if (j4 < 36) {
            __half2 h0 = __floats2half2_rn(acc.x, acc.y);
            __half2 h1 = __floats2half2_rn(acc.z, acc.w);
            __half2* p = (__half2*)(g_TextH + (size_t)n * ROWH + j4 * 4);
            p[0] = h0;
            p[1] = h1;
        } else {
            *(float4*)&g_rootx[n * 16 + (j4 - 36) * 4] = acc;
        }
    }
}

// 8 cooperative lanes per edge over the fp16 table (3 lines/row).
// Lane l: 16B load at row+16l (T d0=l>>1, cols 8(l&1)..+7) and row+128+16l
// (T d0+4, same cols). Each instruction covers a full 128B line per edge.
// shfl_down(4) then (2) folds lanes {l,l+2,l+4,l+6}; lanes 0/1 add xb and
// emit two red4 each (cols 0-7 / 8-15).
__global__ void __launch_bounds__(256)
edge_kernel(const void* __restrict__ ei_raw,
            const float* __restrict__ ea,
            int layer, int do_cnt) {
    int gt = blockIdx.x * blockDim.x + threadIdx.x;
    int e = gt >> 3;           // grid exact: EE*8 == 25000*256
    int l = gt & 7;

    int src, dst;
    if (g_is64) {
        const long long* ei = (const long long*)ei_raw;
        src = (int)ei[e];
        dst = (int)ei[EE + e];
    } else {
        const int* ei = (const int*)ei_raw;
        src = ei[e];
        dst = ei[EE + e];
    }
    // Defensive without breaking warp convergence for the shuffles below.
    bool ok = ((unsigned)src < NN) && ((unsigned)dst < NN);
    if (!ok) src = 0;

    // all 8 lanes of the group load the same ea row (L1 broadcast)
    const float4* eap = (const float4*)(ea + (size_t)e * 8);
    float4 a0 = eap[0], a1 = eap[1];
    int d0 = l >> 1;
    float w0 = (d0 == 0) ? a0.x : (d0 == 1) ? a0.y : (d0 == 2) ? a0.z : a0.w;
    float w1 = (d0 == 0) ? a1.x : (d0 == 1) ? a1.y : (d0 == 2) ? a1.z : a1.w;

    const char* row = (const char*)(g_TextH + (size_t)src * ROWH);
    float4 rA = *(const float4*)(row + l * 16);        // T[d0][8 cols] as 8 halves
    float4 rB = *(const float4*)(row + 128 + l * 16);  // T[d0+4][8 cols]

    float2 q0, q1, q2, q3;
    {
        float2 fa, fb;
        fa = __half22float2(*(__half2*)&rA.x); fb = __half22float2(*(__half2*)&rB.x);
        q0.x = fmaf(w0, fa.x, w1 * fb.x); q0.y = fmaf(w0, fa.y, w1 * fb.y);
        fa = __half22float2(*(__half2*)&rA.y); fb = __half22float2(*(__half2*)&rB.y);
        q1.x = fmaf(w0, fa.x, w1 * fb.x); q1.y = fmaf(w0, fa.y, w1 * fb.y);
        fa = __half22float2(*(__half2*)&rA.z); fb = __half22float2(*(__half2*)&rB.z);
        q2.x = fmaf(w0, fa.x, w1 * fb.x); q2.y = fmaf(w0, fa.y, w1 * fb.y);
        fa = __half22float2(*(__half2*)&rA.w); fb = __half22float2(*(__half2*)&rB.w);
        q3.x = fmaf(w0, fa.x, w1 * fb.x); q3.y = fmaf(w0, fa.y, w1 * fb.y);
    }

    // fold lanes {l, l+2, l+4, l+6} -> lanes 0 (cols 0-7) and 1 (cols 8-15)
    q0.x += __shfl_down_sync(0xffffffffu, q0.x, 4);
    q0.y += __shfl_down_sync(0xffffffffu, q0.y, 4);
    q1.x += __shfl_down_sync(0xffffffffu, q1.x, 4);
    q1.y += __shfl_down_sync(0xffffffffu, q1.y, 4);
    q2.x += __shfl_down_sync(0xffffffffu, q2.x, 4);
    q2.y += __shfl_down_sync(0xffffffffu, q2.y, 4);
    q3.x += __shfl_down_sync(0xffffffffu, q3.x, 4);
    q3.y += __shfl_down_sync(0xffffffffu, q3.y, 4);
    q0.x += __shfl_down_sync(0xffffffffu, q0.x, 2);
    q0.y += __shfl_down_sync(0xffffffffu, q0.y, 2);
    q1.x += __shfl_down_sync(0xffffffffu, q1.x, 2);
    q1.y += __shfl_down_sync(0xffffffffu, q1.y, 2);
    q2.x += __shfl_down_sync(0xffffffffu, q2.x, 2);
    q2.y += __shfl_down_sync(0xffffffffu, q2.y, 2);
    q3.x += __shfl_down_sync(0xffffffffu, q3.x, 2);
    q3.y += __shfl_down_sync(0xffffffffu, q3.y, 2);

    if (l < 2 && ok) {
        // xb for cols 8l..8l+7: halves 128+8l (bytes 256+16l)
        float4 xr = *(const float4*)(row + 256 + l * 16);
        float2 b0 = __half22float2(*(__half2*)&xr.x);
        float2 b1 = __half22float2(*(__half2*)&xr.y);
        float2 b2 = __half22float2(*(__half2*)&xr.z);
        float2 b3 = __half22float2(*(__half2*)&xr.w);
        float* dstp = (layer ? g_agg1 : g_agg0) + (size_t)dst * 16 + l * 8;
        red4(dstp, make_float4(q0.x + b0.x, q0.y + b0.y, q1.x + b1.x, q1.y + b1.y));
        red4(dstp + 4, make_float4(q2.x + b2.x, q2.y + b2.y, q3.x + b3.x, q3.y + b3.y));
        if (do_cnt && l == 0) atomicAdd(&g_cnt[dst], 1.0f);
    }
}

// h[n,o] = relu(agg0[n,o]/max(cnt,1) + rootx[n,o])
__global__ void relu_h_kernel() {
    int idx = blockIdx.x * blockDim.x + threadIdx.x;
    if (idx >= NN * 16) return;
    int n = idx >> 4;
    float c = fmaxf(g_cnt[n], 1.f);
    float v = g_agg0[idx] / c + g_rootx[idx];
    g_h[idx] = fmaxf(v, 0.f);
}

// out[n] = sum_o relu(agg1[n,o]/max(cnt,1) + rootx[n,o]) * head_w[o] + head_b
__global__ void head_kernel(const float* __restrict__ hw,
                            const float* __restrict__ hb,
                            float* __restrict__ out) {
    int n = blockIdx.x * blockDim.x + threadIdx.x;
    if (n >= NN) return;
    float inv = 1.f / fmaxf(g_cnt[n], 1.f);
    const float* ag = g_agg1 + (size_t)n * 16;
    const float* rx = g_rootx + (size_t)n * 16;
    float s = hb[0];
#pragma unroll
    for (int o = 0; o < 16; o++) {
        float v = fmaxf(fmaf(ag[o], inv, rx[o]), 0.f);
        s = fmaf(v, hw[o], s);
    }
    out[n] = s;
}

// ---------------- launch ----------------
extern "C" void kernel_launch(void* const* d_in, const int* in_sizes, int n_in,
                              void* d_out, int out_size) {
    const float* x     = (const float*)d_in[0];
    const void*  ei    = d_in[1];
    const float* ea    = (const float*)d_in[2];
    const float* nn_w0 = (const float*)d_in[3];
    const float* nn_b0 = (const float*)d_in[4];
    const float* root0 = (const float*)d_in[5];
    const float* bias0 = (const float*)d_in[6];
    const float* nn_w1 = (const float*)d_in[7];
    const float* nn_b1 = (const float*)d_in[8];
    const float* root1 = (const float*)d_in[9];
    const float* bias1 = (const float*)d_in[10];
    const float* headw = (const float*)d_in[11];
    const float* headb = (const float*)d_in[12];
    float* out = (float*)d_out;

    const int TB = 256;
    const int EB = (EE * 8 + TB - 1) / TB;   // 8 lanes per edge

    detect_kernel<<<1, 32>>>(ei);
    zero_kernel<<<1024, TB>>>();
    node_prep_kernel<<<1184, TB>>>(x, nn_w0, nn_b0, root0, bias0);
    edge_kernel<<<EB, TB>>>(ei, ea, /*layer=*/0, /*do_cnt=*/1);
    relu_h_kernel<<<(NN * 16 + TB - 1) / TB, TB>>>();
    node_prep_kernel<<<1184, TB>>>(nullptr, nn_w1, nn_b1, root1, bias1);
    edge_kernel<<<EB, TB>>>(ei, ea, /*layer=*/1, /*do_cnt=*/0);
    head_kernel<<<(NN + TB - 1) / TB, TB>>>(headw, headb, out);
}

// round 8
// speedup vs baseline: 1.1014x; 1.1014x over previous
#include <cuda_runtime.h>

// Problem constants
#define NN   50000
#define EE   800000
#define ROW  160      // Text row stride in floats: [T 0..127 | xb 128..143 | rootx 144..159]
                      // 640 B/row = 5 x 128B lines; line k holds d=2k,2k+1 (k<4), line 4 = xb|rootx.

// ---------------- scratch (static device memory; no runtime allocation) ----------------
__device__ float g_Text[(size_t)NN * ROW];  // 32 MB, fits L2
__device__ float g_h[NN * 16];
__device__ float g_agg0[NN * 16];
__device__ float g_agg1[NN * 16];
__device__ float g_cnt[NN];
__device__ int   g_is64;   // 1 if edge_index is int64, 0 if int32

// ---------------- helpers ----------------
__device__ __forceinline__ float4 f4fma(float s, float4 a, float4 b) {
    b.x = fmaf(s, a.x, b.x);
    b.y = fmaf(s, a.y, b.y);
    b.z = fmaf(s, a.z, b.z);
    b.w = fmaf(s, a.w, b.w);
    return b;
}

// vectorized no-return atomic add (sm_90+, PTX ISA 8.1)
__device__ __forceinline__ void red4(float* p, float4 v) {
    asm volatile("red.global.add.v4.f32 [%0], {%1, %2, %3, %4};"
                 :: "l"(p), "f"(v.x), "f"(v.y), "f"(v.z), "f"(v.w)
                 : "memory");
}

// ---------------- kernels ----------------

// Probe edge_index dtype: int64 vs JAX-x64-disabled int32. Parallel (1 warp).
__global__ void detect_kernel(const void* ei) {
    const unsigned long long* p = (const unsigned long long*)ei;
    int t = threadIdx.x;
    bool bad = (p[t] >= (unsigned long long)NN) ||
               (p[t + 32] >= (unsigned long long)NN);
    unsigned m = __ballot_sync(0xffffffffu, bad);
    if (t == 0) g_is64 = (m == 0) ? 1 : 0;
}

__global__ void zero_kernel() {
    int idx = blockIdx.x * blockDim.x + threadIdx.x;
    int stride = gridDim.x * blockDim.x;
    for (int i = idx; i < NN * 16; i += stride) {
        g_agg0[i] = 0.f;
        g_agg1[i] = 0.f;
    }
    for (int i = idx; i < NN; i += stride) g_cnt[i] = 0.f;
}

// Build Text[n, 0..159]:
//   j in [0,128):   T[n,d,o]    = sum_i in[n,i] * nn_w[d*256 + i*16 + o]   (d=j>>4, o=j&15)
//   j in [128,144): xb[n,o]     = sum_i in[n,i] * nn_b[i*16 + o]
//   j in [144,160): rootx[n,o]  = sum_i in[n,i] * root[i*16 + o] + bias[o]
// 2 nodes per thread: each smem weight read feeds two FMA4s (halves LDS traffic,
// which is this kernel's crossbar-bound cost).
__global__ void __launch_bounds__(256)
node_prep_kernel(const float* __restrict__ xin,   // nullptr -> use g_h
                 const float* __restrict__ nw,
                 const float* __restrict__ nb,
                 const float* __restrict__ rt,
                 const float* __restrict__ bs) {
    __shared__ float Wc[16 * ROW];
    __shared__ float Bc[ROW];
    const float* in = (xin != nullptr) ? xin : g_h;

    for (int t = threadIdx.x; t < 16 * ROW; t += blockDim.x) {
        int i = t / ROW, j = t % ROW;
        float w;
        if (j < 128) {
            int d = j >> 4, o = j & 15;
            w = nw[d * 256 + i * 16 + o];
        } else if (j < 144) {
            int o = j - 128;
            w = nb[i * 16 + o];
        } else {
            int o = j - 144;
            w = rt[i * 16 + o];
        }
        Wc[t] = w;
    }
    for (int t = threadIdx.x; t < ROW; t += blockDim.x)
        Bc[t] = (t >= 144) ? bs[t - 144] : 0.f;
    __syncthreads();

    const int total = (NN / 2) * (ROW / 4);  // one thread per float4 of 2 nodes
    for (int g = blockIdx.x * blockDim.x + threadIdx.x; g < total;
         g += gridDim.x * blockDim.x) {
        int pair = g / (ROW / 4);
        int j4 = g % (ROW / 4);
        int n0 = pair * 2;
        const float4* xr0 = (const float4*)(in + (size_t)n0 * 16);
        const float4* xr1 = (const float4*)(in + (size_t)(n0 + 1) * 16);
        float4 a0 = xr0[0], a1 = xr0[1], a2 = xr0[2], a3 = xr0[3];
        float4 b0 = xr1[0], b1 = xr1[1], b2 = xr1[2], b3 = xr1[3];
        float xv0[16] = {a0.x, a0.y, a0.z, a0.w, a1.x, a1.y, a1.z, a1.w,
                         a2.x, a2.y, a2.z, a2.w, a3.x, a3.y, a3.z, a3.w};
        float xv1[16] = {b0.x, b0.y, b0.z, b0.w, b1.x, b1.y, b1.z, b1.w,
                         b2.x, b2.y, b2.z, b2.w, b3.x, b3.y, b3.z, b3.w};
        float4 base = *(const float4*)&Bc[j4 * 4];
        float4 acc0 = base, acc1 = base;
#pragma unroll
        for (int i = 0; i < 16; i++) {
            float4 w = *(const float4*)&Wc[i * ROW + j4 * 4];
            acc0 = f4fma(xv0[i], w, acc0);
            acc1 = f4fma(xv1[i], w, acc1);
        }
        *(float4*)&g_Text[(size_t)n0 * ROW + j4 * 4] = acc0;
        *(float4*)&g_Text[(size_t)(n0 + 1) * ROW + j4 * 4] = acc1;
    }
}

// 8 cooperative lanes per edge (fp32 table). Lane l loads float4 at
// row + k*32 + l*4 for k=0..4 -> each load instruction covers one full 128B
// line per edge. h=l>>2 selects even(0)/odd(1) d's; lanes (l, l+4) hold all
// 8 d's of column group l&3, combined with one shfl_down(4). Line 4 gives
// xb to h=0 lanes for free.
__global__ void __launch_bounds__(256)
edge_kernel(const void* __restrict__ ei_raw,
            const float* __restrict__ ea,
            int layer, int do_cnt) {
    int gt = blockIdx.x * blockDim.x + threadIdx.x;
    int e = gt >> 3;               // grid exact: EE*8 == 25000*256
    int l = gt & 7;
    int h = l >> 2;                // 0: even d's + xb; 1: odd d's
    int cg = (l & 3) * 4;          // output column offset this lane-pair owns

    int src, dst;
    if (g_is64) {
        const long long* ei = (const long long*)ei_raw;
        src = (int)ei[e];
        dst = (int)ei[EE + e];
    } else {
        const int* ei = (const int*)ei_raw;
        src = ei[e];
        dst = ei[EE + e];
    }
    // Defensive without breaking warp convergence for the shuffles below.
    bool ok = ((unsigned)src < NN) && ((unsigned)dst < NN);
    if (!ok) src = 0;

    // all 8 lanes of the group load the same ea row (L1 broadcast)
    const float4* eap = (const float4*)(ea + (size_t)e * 8);
    float4 a0 = eap[0], a1 = eap[1];
    float w0 = h ? a0.y : a0.x;    // ea[0+h]
    float w1 = h ? a0.w : a0.z;    // ea[2+h]
    float w2 = h ? a1.y : a1.x;    // ea[4+h]
    float w3 = h ? a1.w : a1.z;    // ea[6+h]

    const float* Tr = g_Text + (size_t)src * ROW + l * 4;
    float4 t0 = *(const float4*)(Tr + 0);     // T[0+h][cg..]
    float4 t1 = *(const float4*)(Tr + 32);    // T[2+h][cg..]
    float4 t2 = *(const float4*)(Tr + 64);    // T[4+h][cg..]
    float4 t3 = *(const float4*)(Tr + 96);    // T[6+h][cg..]
    float4 t4 = *(const float4*)(Tr + 128);   // h=0: xb[cg..]; h=1: rootx (unused)

    float4 p = h ? make_float4(0.f, 0.f, 0.f, 0.f) : t4;
    p = f4fma(w0, t0, p);
    p = f4fma(w1, t1, p);
    p = f4fma(w2, t2, p);
    p = f4fma(w3, t3, p);

    // combine even/odd halves: lane l += lane l+4 (converged, full mask)
    p.x += __shfl_down_sync(0xffffffffu, p.x, 4);
    p.y += __shfl_down_sync(0xffffffffu, p.y, 4);
    p.z += __shfl_down_sync(0xffffffffu, p.z, 4);
    p.w += __shfl_down_sync(0xffffffffu, p.w, 4);

    if (h == 0 && ok) {
        float* dstp = (layer ? g_agg1 : g_agg0) + (size_t)dst * 16 + cg;
        red4(dstp, p);
        if (do_cnt && l == 0) atomicAdd(&g_cnt[dst], 1.0f);
    }
}

// h[n,o] = relu(agg0[n,o]/max(cnt,1) + rootx0[n,o])
__global__ void relu_h_kernel() {
    int idx = blockIdx.x * blockDim.x + threadIdx.x;
    if (idx >= NN * 16) return;
    int n = idx >> 4, o = idx & 15;
    float c = fmaxf(g_cnt[n], 1.f);
    float v = g_agg0[idx] / c + g_Text[(size_t)n * ROW + 144 + o];
    g_h[idx] = fmaxf(v, 0.f);
}

// out[n] = sum_o relu(agg1[n,o]/max(cnt,1) + rootx1[n,o]) * head_w[o] + head_b
__global__ void head_kernel(const float* __restrict__ hw,
                            const float* __restrict__ hb,
                            float* __restrict__ out) {
    int n = blockIdx.x * blockDim.x + threadIdx.x;
    if (n >= NN) return;
    float inv = 1.f / fmaxf(g_cnt[n], 1.f);
    const float* ag = g_agg1 + (size_t)n * 16;
    const float* rx = g_Text + (size_t)n * ROW + 144;
    float s = hb[0];
#pragma unroll
    for (int o = 0; o < 16; o++) {
        float v = fmaxf(fmaf(ag[o], inv, rx[o]), 0.f);
        s = fmaf(v, hw[o], s);
    }
    out[n] = s;
}

// ---------------- launch ----------------
extern "C" void kernel_launch(void* const* d_in, const int* in_sizes, int n_in,
                              void* d_out, int out_size) {
    const float* x     = (const float*)d_in[0];
    const void*  ei    = d_in[1];
    const float* ea    = (const float*)d_in[2];
    const float* nn_w0 = (const float*)d_in[3];
    const float* nn_b0 = (const float*)d_in[4];
    const float* root0 = (const float*)d_in[5];
    const float* bias0 = (const float*)d_in[6];
    const float* nn_w1 = (const float*)d_in[7];
    const float* nn_b1 = (const float*)d_in[8];
    const float* root1 = (const float*)d_in[9];
    const float* bias1 = (const float*)d_in[10];
    const float* headw = (const float*)d_in[11];
    const float* headb = (const float*)d_in[12];
    float* out = (float*)d_out;

    const int TB = 256;
    const int EB = (EE * 8 + TB - 1) / TB;   // 8 lanes per edge

    detect_kernel<<<1, 32>>>(ei);
    zero_kernel<<<1024, TB>>>();
    node_prep_kernel<<<1184, TB>>>(x, nn_w0, nn_b0, root0, bias0);
    edge_kernel<<<EB, TB>>>(ei, ea, /*layer=*/0, /*do_cnt=*/1);
    relu_h_kernel<<<(NN * 16 + TB - 1) / TB, TB>>>();
    node_prep_kernel<<<1184, TB>>>(nullptr, nn_w1, nn_b1, root1, bias1);
    edge_kernel<<<EB, TB>>>(ei, ea, /*layer=*/1, /*do_cnt=*/0);
    head_kernel<<<(NN + TB - 1) / TB, TB>>>(headw, headb, out);
}

// round 9
// speedup vs baseline: 1.3214x; 1.1998x over previous
#include <cuda_runtime.h>
#include <cuda_fp16.h>

// Problem constants
#define NN    50000
#define EE    800000
#define ROW   160     // logical node-prep row in floats: [T 0..127 | xb 128..143 | rootx 144..159]
#define ROWH  192     // fp16 table stride in halves = 384 B = 3 x 128B lines.
                      // o-major permuted: slot s (16 slots x 8 halves), s<8 -> o=2s, s>=8 -> o=2(s-8)+1.
                      // half idx = s*8 + d. Line0 = slots 0..7, line1 = slots 8..15, line2 unused pad.

// ---------------- scratch (static device memory; no runtime allocation) ----------------
__device__ __half g_TextH[(size_t)NN * ROWH];   // 19.2 MB, fits L2
__device__ float  g_xb[NN * 16];                // fp32 xb side table
__device__ float  g_rootx[NN * 16];
__device__ float  g_h[NN * 16];
__device__ float  g_agg0[NN * 16];
__device__ float  g_agg1[NN * 16];
__device__ float  g_cnt[NN];
__device__ int    g_is64;   // 1 if edge_index is int64, 0 if int32

// ---------------- helpers ----------------
__device__ __forceinline__ float4 f4fma(float s, float4 a, float4 b) {
    b.x = fmaf(s, a.x, b.x);
    b.y = fmaf(s, a.y, b.y);
    b.z = fmaf(s, a.z, b.z);
    b.w = fmaf(s, a.w, b.w);
    return b;
}

// vectorized no-return atomic adds (sm_90+, PTX ISA 8.1)
__device__ __forceinline__ void red2(float* p, float a, float b) {
    asm volatile("red.global.add.v2.f32 [%0], {%1, %2};"
                 :: "l"(p), "f"(a), "f"(b) : "memory");
}

// ---------------- kernels ----------------

// Probe edge_index dtype: int64 vs JAX-x64-disabled int32. Parallel (1 warp).
__global__ void detect_kernel(const void* ei) {
    const unsigned long long* p = (const unsigned long long*)ei;
    int t = threadIdx.x;
    bool bad = (p[t] >= (unsigned long long)NN) ||
               (p[t + 32] >= (unsigned long long)NN);
    unsigned m = __ballot_sync(0xffffffffu, bad);
    if (t == 0) g_is64 = (m == 0) ? 1 : 0;
}

__global__ void zero_kernel() {
    int idx = blockIdx.x * blockDim.x + threadIdx.x;
    int stride = gridDim.x * blockDim.x;
    for (int i = idx; i < NN * 16; i += stride) {
        g_agg0[i] = 0.f;
        g_agg1[i] = 0.f;
    }
    for (int i = idx; i < NN; i += stride) g_cnt[i] = 0.f;
}

// Build per-node tables (2 nodes per thread to halve smem LDS traffic):
//   j4 in [0,32):  T float4 (d=j4>>2, o=(j4&3)*4..+3) -> permuted fp16 slots in g_TextH
//   j4 in [32,36): xb  -> fp32 g_xb
//   j4 in [36,40): rootx -> fp32 g_rootx
__global__ void __launch_bounds__(256)
node_prep_kernel(const float* __restrict__ xin,   // nullptr -> use g_h
                 const float* __restrict__ nw,
                 const float* __restrict__ nb,
                 const float* __restrict__ rt,
                 const float* __restrict__ bs) {
    __shared__ float Wc[16 * ROW];
    __shared__ float Bc[ROW];
    const float* in = (xin != nullptr) ? xin : g_h;

    for (int t = threadIdx.x; t < 16 * ROW; t += blockDim.x) {
        int i = t / ROW, j = t % ROW;
        float w;
        if (j < 128) {
            int d = j >> 4, o = j & 15;
            w = nw[d * 256 + i * 16 + o];
        } else if (j < 144) {
            int o = j - 128;
            w = nb[i * 16 + o];
        } else {
            int o = j - 144;
            w = rt[i * 16 + o];
        }
        Wc[t] = w;
    }
    for (int t = threadIdx.x; t < ROW; t += blockDim.x)
        Bc[t] = (t >= 144) ? bs[t - 144] : 0.f;
    __syncthreads();

    const int total = (NN / 2) * (ROW / 4);  // one thread per float4 of 2 nodes
    for (int g = blockIdx.x * blockDim.x + threadIdx.x; g < total;
         g += gridDim.x * blockDim.x) {
        int pair = g / (ROW / 4);
        int j4 = g % (ROW / 4);
        int n0 = pair * 2;
        const float4* xr0 = (const float4*)(in + (size_t)n0 * 16);
        const float4* xr1 = (const float4*)(in + (size_t)(n0 + 1) * 16);
        float4 a0 = xr0[0], a1 = xr0[1], a2 = xr0[2], a3 = xr0[3];
        float4 b0 = xr1[0], b1 = xr1[1], b2 = xr1[2], b3 = xr1[3];
        float xv0[16] = {a0.x, a0.y, a0.z, a0.w, a1.x, a1.y, a1.z, a1.w,
                         a2.x, a2.y, a2.z, a2.w, a3.x, a3.y, a3.z, a3.w};
        float xv1[16] = {b0.x, b0.y, b0.z, b0.w, b1.x, b1.y, b1.z, b1.w,
                         b2.x, b2.y, b2.z, b2.w, b3.x, b3.y, b3.z, b3.w};
        float4 base = *(const float4*)&Bc[j4 * 4];
        float4 acc0 = base, acc1 = base;
#pragma unroll
        for (int i = 0; i < 16; i++) {
            float4 w = *(const float4*)&Wc[i * ROW + j4 * 4];
            acc0 = f4fma(xv0[i], w, acc0);
            acc1 = f4fma(xv1[i], w, acc1);
        }
        if (j4 < 32) {
            // T float4: d = j4>>2, columns o0..o0+3 with o0=(j4&3)*4.
            // Permuted slot layout: even o -> slot o/2 (halves s*8+d),
            //                       odd  o -> slot 8+o/2.
            // base half index for (d, o0): (o0/2)*8 + d = (j4&3)*16 + (j4>>2)
            int bi = (j4 & 3) * 16 + (j4 >> 2);
            __half* r0 = g_TextH + (size_t)n0 * ROWH;
            __half* r1 = g_TextH + (size_t)(n0 + 1) * ROWH;
            r0[bi]      = __float2half_rn(acc0.x);   // o0   (even)
            r0[bi + 64] = __float2half_rn(acc0.y);   // o0+1 (odd)
            r0[bi + 8]  = __float2half_rn(acc0.z);   // o0+2 (even)
            r0[bi + 72] = __float2half_rn(acc0.w);   // o0+3 (odd)
            r1[bi]      = __float2half_rn(acc1.x);
            r1[bi + 64] = __float2half_rn(acc1.y);
            r1[bi + 8]  = __float2half_rn(acc1.z);
            r1[bi + 72] = __float2half_rn(acc1.w);
        } else if (j4 < 36) {
            int o0 = (j4 - 32) * 4;
            *(float4*)&g_xb[n0 * 16 + o0] = acc0;
            *(float4*)&g_xb[(n0 + 1) * 16 + o0] = acc1;
        } else {
            int o0 = (j4 - 36) * 4;
            *(float4*)&g_rootx[n0 * 16 + o0] = acc0;
            *(float4*)&g_rootx[(n0 + 1) * 16 + o0] = acc1;
        }
    }
}

// 8 cooperative lanes per edge, shuffle-free fp16 o-major gather.
// Lane l: 16B load at row+16l      -> slot l    = T[:, o=2l]   (8 halves, d0..7)
//         16B load at row+128+16l  -> slot 8+l  = T[:, o=2l+1]
// Each instruction covers exactly one 128B line per edge. Lane computes
// msg[2l], msg[2l+1] fully in fp32 (8 H2F2 cvts + 16 FMA), adds fp32 xb via
// one float2 load, and issues one red.v2 (64B/edge contiguous scatter).
__global__ void __launch_bounds__(256)
edge_kernel(const void* __restrict__ ei_raw,
            const float* __restrict__ ea,
            int layer, int do_cnt) {
    int gt = blockIdx.x * blockDim.x + threadIdx.x;
    int e = gt >> 3;               // grid exact: EE*8 == 25000*256
    int l = gt & 7;

    int src, dst;
    if (g_is64) {
        const long long* ei = (const long long*)ei_raw;
        src = (int)ei[e];
        dst = (int)ei[EE + e];
    } else {
        const int* ei = (const int*)ei_raw;
        src = ei[e];
        dst = ei[EE + e];
    }
    bool ok = ((unsigned)src < NN) && ((unsigned)dst < NN);
    if (!ok) src = 0;

    // all 8 lanes of the group load the same ea row (L1 broadcast)
    const float4* eap = (const float4*)(ea + (size_t)e * 8);
    float4 a0 = eap[0], a1 = eap[1];

    const char* row = (const char*)(g_TextH + (size_t)src * ROWH);
    float4 rA = *(const float4*)(row + 16 * l);        // T[:, 2l]
    float4 rB = *(const float4*)(row + 128 + 16 * l);  // T[:, 2l+1]

    float mA, mB;
    {
        float2 f0 = __half22float2(*(__half2*)&rA.x);  // d0,d1
        float2 f1 = __half22float2(*(__half2*)&rA.y);  // d2,d3
        float2 f2 = __half22float2(*(__half2*)&rA.z);  // d4,d5
        float2 f3 = __half22float2(*(__half2*)&rA.w);  // d6,d7
        mA = f0.x * a0.x;
        mA = fmaf(f0.y, a0.y, mA);
        mA = fmaf(f1.x, a0.z, mA);
        mA = fmaf(f1.y, a0.w, mA);
        mA = fmaf(f2.x, a1.x, mA);
        mA = fmaf(f2.y, a1.y, mA);
        mA = fmaf(f3.x, a1.z, mA);
        mA = fmaf(f3.y, a1.w, mA);
    }
    {
        float2 f0 = __half22float2(*(__half2*)&rB.x);
        float2 f1 = __half22float2(*(__half2*)&rB.y);
        float2 f2 = __half22float2(*(__half2*)&rB.z);
        float2 f3 = __half22float2(*(__half2*)&rB.w);
        mB = f0.x * a0.x;
        mB = fmaf(f0.y, a0.y, mB);
        mB = fmaf(f1.x, a0.z, mB);
        mB = fmaf(f1.y, a0.w, mB);
        mB = fmaf(f2.x, a1.x, mB);
        mB = fmaf(f2.y, a1.y, mB);
        mB = fmaf(f3.x, a1.z, mB);
        mB = fmaf(f3.y, a1.w, mB);
    }

    // fp32 xb for this lane's two columns
    float2 xb2 = *(const float2*)(g_xb + (size_t)src * 16 + 2 * l);
    mA += xb2.x;
    mB += xb2.y;

    if (ok) {
        float* dstp = (layer ? g_agg1 : g_agg0) + (size_t)dst * 16 + 2 * l;
        red2(dstp, mA, mB);
        if (do_cnt && l == 0) atomicAdd(&g_cnt[dst], 1.0f);
    }
}

// h[n,o] = relu(agg0[n,o]/max(cnt,1) + rootx[n,o])
__global__ void relu_h_kernel() {
    int idx = blockIdx.x * blockDim.x + threadIdx.x;
    if (idx >= NN * 16) return;
    int n = idx >> 4;
    float c = fmaxf(g_cnt[n], 1.f);
    float v = g_agg0[idx] / c + g_rootx[idx];
    g_h[idx] = fmaxf(v, 0.f);
}

// out[n] = sum_o relu(agg1[n,o]/max(cnt,1) + rootx[n,o]) * head_w[o] + head_b
__global__ void head_kernel(const float* __restrict__ hw,
                            const float* __restrict__ hb,
                            float* __restrict__ out) {
    int n = blockIdx.x * blockDim.x + threadIdx.x;
    if (n >= NN) return;
    float inv = 1.f / fmaxf(g_cnt[n], 1.f);
    const float* ag = g_agg1 + (size_t)n * 16;
    const float* rx = g_rootx + (size_t)n * 16;
    float s = hb[0];
#pragma unroll
    for (int o = 0; o < 16; o++) {
        float v = fmaxf(fmaf(ag[o], inv, rx[o]), 0.f);
        s = fmaf(v, hw[o], s);
    }
    out[n] = s;
}

// ---------------- launch ----------------
extern "C" void kernel_launch(void* const* d_in, const int* in_sizes, int n_in,
                              void* d_out, int out_size) {
    const float* x     = (const float*)d_in[0];
    const void*  ei    = d_in[1];
    const float* ea    = (const float*)d_in[2];
    const float* nn_w0 = (const float*)d_in[3];
    const float* nn_b0 = (const float*)d_in[4];
    const float* root0 = (const float*)d_in[5];
    const float* bias0 = (const float*)d_in[6];
    const float* nn_w1 = (const float*)d_in[7];
    const float* nn_b1 = (const float*)d_in[8];
    const float* root1 = (const float*)d_in[9];
    const float* bias1 = (const float*)d_in[10];
    const float* headw = (const float*)d_in[11];
    const float* headb = (const float*)d_in[12];
    float* out = (float*)d_out;

    const int TB = 256;
    const int EB = (EE * 8 + TB - 1) / TB;   // 8 lanes per edge

    detect_kernel<<<1, 32>>>(ei);
    zero_kernel<<<1024, TB>>>();
    node_prep_kernel<<<1184, TB>>>(x, nn_w0, nn_b0, root0, bias0);
    edge_kernel<<<EB, TB>>>(ei, ea, /*layer=*/0, /*do_cnt=*/1);
    relu_h_kernel<<<(NN * 16 + TB - 1) / TB, TB>>>();
    node_prep_kernel<<<1184, TB>>>(nullptr, nn_w1, nn_b1, root1, bias1);
    edge_kernel<<<EB, TB>>>(ei, ea, /*layer=*/1, /*do_cnt=*/0);
    head_kernel<<<(NN + TB - 1) / TB, TB>>>(headw, headb, out);
}

// round 10
// speedup vs baseline: 1.3451x; 1.0179x over previous
#include <cuda_runtime.h>
#include <cuda_fp16.h>

// Problem constants
#define NN    50000
#define EE    800000
#define ROW   160     // logical node-prep row in floats: [T 0..127 | xb 128..143 | rootx 144..159]
#define ROWH  128     // fp16 table stride in halves = 256 B = 2 x 128B lines.
                      // o-major permuted: slot s (16 slots x 8 halves), s<8 -> o=2s, s>=8 -> o=2(s-8)+1.
                      // half idx = s*8 + d. Line0 = slots 0..7 (even cols), line1 = slots 8..15 (odd cols).

// ---------------- scratch (static device memory; no runtime allocation) ----------------
__device__ __half g_TextH[(size_t)NN * ROWH];   // 12.8 MB, fits L2 easily
__device__ float  g_xb[NN * 16];                // fp32 xb side table
__device__ float  g_rootx[NN * 16];
__device__ float  g_h[NN * 16];
__device__ float  g_agg0[NN * 16];
__device__ float  g_agg1[NN * 16];
__device__ float  g_cnt[NN];
__device__ int    g_is64;   // 1 if edge_index is int64, 0 if int32

// ---------------- helpers ----------------
__device__ __forceinline__ float4 f4fma(float s, float4 a, float4 b) {
    b.x = fmaf(s, a.x, b.x);
    b.y = fmaf(s, a.y, b.y);
    b.z = fmaf(s, a.z, b.z);
    b.w = fmaf(s, a.w, b.w);
    return b;
}

// vectorized no-return atomic add (sm_90+, PTX ISA 8.1)
__device__ __forceinline__ void red2(float* p, float a, float b) {
    asm volatile("red.global.add.v2.f32 [%0], {%1, %2};"
                 :: "l"(p), "f"(a), "f"(b) : "memory");
}

// ---------------- kernels ----------------

// Zero agg0 + cnt; block 0 / warp 0 also probes edge_index dtype
// (int64 vs JAX-x64-disabled int32).
__global__ void zero_detect_kernel(const void* ei) {
    if (blockIdx.x == 0 && threadIdx.x < 32) {
        const unsigned long long* p = (const unsigned long long*)ei;
        int t = threadIdx.x;
        bool bad = (p[t] >= (unsigned long long)NN) ||
                   (p[t + 32] >= (unsigned long long)NN);
        unsigned m = __ballot_sync(0xffffffffu, bad);
        if (t == 0) g_is64 = (m == 0) ? 1 : 0;
    }
    int idx = blockIdx.x * blockDim.x + threadIdx.x;
    int stride = gridDim.x * blockDim.x;
    for (int i = idx; i < NN * 16; i += stride) g_agg0[i] = 0.f;
    for (int i = idx; i < NN; i += stride) g_cnt[i] = 0.f;
}

// Build per-node tables (2 nodes per thread to halve smem LDS traffic):
//   j4 in [0,32):  T float4 (d=j4>>2, o=(j4&3)*4..+3) -> permuted fp16 slots in g_TextH
//   j4 in [32,36): xb  -> fp32 g_xb
//   j4 in [36,40): rootx -> fp32 g_rootx
__global__ void __launch_bounds__(256)
node_prep_kernel(const float* __restrict__ xin,   // nullptr -> use g_h
                 const float* __restrict__ nw,
                 const float* __restrict__ nb,
                 const float* __restrict__ rt,
                 const float* __restrict__ bs) {
    __shared__ float Wc[16 * ROW];
    __shared__ float Bc[ROW];
    const float* in = (xin != nullptr) ? xin : g_h;

    for (int t = threadIdx.x; t < 16 * ROW; t += blockDim.x) {
        int i = t / ROW, j = t % ROW;
        float w;
        if (j < 128) {
            int d = j >> 4, o = j & 15;
            w = nw[d * 256 + i * 16 + o];
        } else if (j < 144) {
            int o = j - 128;
            w = nb[i * 16 + o];
        } else {
            int o = j - 144;
            w = rt[i * 16 + o];
        }
        Wc[t] = w;
    }
    for (int t = threadIdx.x; t < ROW; t += blockDim.x)
        Bc[t] = (t >= 144) ? bs[t - 144] : 0.f;
    __syncthreads();

    const int total = (NN / 2) * (ROW / 4);  // one thread per float4 of 2 nodes
    for (int g = blockIdx.x * blockDim.x + threadIdx.x; g < total;
         g += gridDim.x * blockDim.x) {
        int pair = g / (ROW / 4);
        int j4 = g % (ROW / 4);
        int n0 = pair * 2;
        const float4* xr0 = (const float4*)(in + (size_t)n0 * 16);
        const float4* xr1 = (const float4*)(in + (size_t)(n0 + 1) * 16);
        float4 a0 = xr0[0], a1 = xr0[1], a2 = xr0[2], a3 = xr0[3];
        float4 b0 = xr1[0], b1 = xr1[1], b2 = xr1[2], b3 = xr1[3];
        float xv0[16] = {a0.x, a0.y, a0.z, a0.w, a1.x, a1.y, a1.z, a1.w,
                         a2.x, a2.y, a2.z, a2.w, a3.x, a3.y, a3.z, a3.w};
        float xv1[16] = {b0.x, b0.y, b0.z, b0.w, b1.x, b1.y, b1.z, b1.w,
                         b2.x, b2.y, b2.z, b2.w, b3.x, b3.y, b3.z, b3.w};
        float4 base = *(const float4*)&Bc[j4 * 4];
        float4 acc0 = base, acc1 = base;
#pragma unroll
        for (int i = 0; i < 16; i++) {
            float4 w = *(const float4*)&Wc[i * ROW + j4 * 4];
            acc0 = f4fma(xv0[i], w, acc0);
            acc1 = f4fma(xv1[i], w, acc1);
        }
        if (j4 < 32) {
            // T float4: d = j4>>2, columns o0..o0+3 with o0=(j4&3)*4.
            // Permuted slot layout: even o -> slot o/2 (halves s*8+d),
            //                       odd  o -> slot 8+o/2.
            // base half index for (d, o0): (o0/2)*8 + d = (j4&3)*16 + (j4>>2)
            int bi = (j4 & 3) * 16 + (j4 >> 2);
            __half* r0 = g_TextH + (size_t)n0 * ROWH;
            __half* r1 = g_TextH + (size_t)(n0 + 1) * ROWH;
            r0[bi]      = __float2half_rn(acc0.x);   // o0   (even)
            r0[bi + 64] = __float2half_rn(acc0.y);   // o0+1 (odd)
            r0[bi + 8]  = __float2half_rn(acc0.z);   // o0+2 (even)
            r0[bi + 72] = __float2half_rn(acc0.w);   // o0+3 (odd)
            r1[bi]      = __float2half_rn(acc1.x);
            r1[bi + 64] = __float2half_rn(acc1.y);
            r1[bi + 8]  = __float2half_rn(acc1.z);
            r1[bi + 72] = __float2half_rn(acc1.w);
        } else if (j4 < 36) {
            int o0 = (j4 - 32) * 4;
            *(float4*)&g_xb[n0 * 16 + o0] = acc0;
            *(float4*)&g_xb[(n0 + 1) * 16 + o0] = acc1;
        } else {
            int o0 = (j4 - 36) * 4;
            *(float4*)&g_rootx[n0 * 16 + o0] = acc0;
            *(float4*)&g_rootx[(n0 + 1) * 16 + o0] = acc1;
        }
    }
}

// 8 cooperative lanes per edge, shuffle-free fp16 o-major gather.
// Lane l: 16B load at row+16l      -> slot l    = T[:, o=2l]   (8 halves, d0..7)
//         16B load at row+128+16l  -> slot 8+l  = T[:, o=2l+1]
// Each instruction covers exactly one 128B line per edge. Lane computes
// msg[2l], msg[2l+1] fully in fp32 (8 H2F2 cvts + 16 FMA), adds fp32 xb via
// one float2 load, and issues one red.v2 (64B/edge contiguous scatter).
__global__ void __launch_bounds__(256)
edge_kernel(const void* __restrict__ ei_raw,
            const float* __restrict__ ea,
            int layer, int do_cnt) {
    int gt = blockIdx.x * blockDim.x + threadIdx.x;
    int e = gt >> 3;               // grid exact: EE*8 == 25000*256
    int l = gt & 7;

    int src, dst;
    if (g_is64) {
        const long long* ei = (const long long*)ei_raw;
        src = (int)ei[e];
        dst = (int)ei[EE + e];
    } else {
        const int* ei = (const int*)ei_raw;
        src = ei[e];
        dst = ei[EE + e];
    }
    bool ok = ((unsigned)src < NN) && ((unsigned)dst < NN);
    if (!ok) src = 0;

    // all 8 lanes of the group load the same ea row (L1 broadcast)
    const float4* eap = (const float4*)(ea + (size_t)e * 8);
    float4 a0 = eap[0], a1 = eap[1];

    const char* row = (const char*)(g_TextH + (size_t)src * ROWH);
    float4 rA = *(const float4*)(row + 16 * l);        // T[:, 2l]
    float4 rB = *(const float4*)(row + 128 + 16 * l);  // T[:, 2l+1]

    float mA, mB;
    {
        float2 f0 = __half22float2(*(__half2*)&rA.x);  // d0,d1
        float2 f1 = __half22float2(*(__half2*)&rA.y);  // d2,d3
        float2 f2 = __half22float2(*(__half2*)&rA.z);  // d4,d5
        float2 f3 = __half22float2(*(__half2*)&rA.w);  // d6,d7
        mA = f0.x * a0.x;
        mA = fmaf(f0.y, a0.y, mA);
        mA = fmaf(f1.x, a0.z, mA);
        mA = fmaf(f1.y, a0.w, mA);
        mA = fmaf(f2.x, a1.x, mA);
        mA = fmaf(f2.y, a1.y, mA);
        mA = fmaf(f3.x, a1.z, mA);
        mA = fmaf(f3.y, a1.w, mA);
    }
    {
        float2 f0 = __half22float2(*(__half2*)&rB.x);
        float2 f1 = __half22float2(*(__half2*)&rB.y);
        float2 f2 = __half22float2(*(__half2*)&rB.z);
        float2 f3 = __half22float2(*(__half2*)&rB.w);
        mB = f0.x * a0.x;
        mB = fmaf(f0.y, a0.y, mB);
        mB = fmaf(f1.x, a0.z, mB);
        mB = fmaf(f1.y, a0.w, mB);
        mB = fmaf(f2.x, a1.x, mB);
        mB = fmaf(f2.y, a1.y, mB);
        mB = fmaf(f3.x, a1.z, mB);
        mB = fmaf(f3.y, a1.w, mB);
    }

    // fp32 xb for this lane's two columns
    float2 xb2 = *(const float2*)(g_xb + (size_t)src * 16 + 2 * l);
    mA += xb2.x;
    mB += xb2.y;

    if (ok) {
        float* dstp = (layer ? g_agg1 : g_agg0) + (size_t)dst * 16 + 2 * l;
        red2(dstp, mA, mB);
        if (do_cnt && l == 0) atomicAdd(&g_cnt[dst], 1.0f);
    }
}

// h[n,o] = relu(agg0[n,o]/max(cnt,1) + rootx[n,o]); also zeroes agg1 for layer 1.
__global__ void relu_h_kernel() {
    int idx = blockIdx.x * blockDim.x + threadIdx.x;
    if (idx >= NN * 16) return;
    int n = idx >> 4;
    float c = fmaxf(g_cnt[n], 1.f);
    float v = g_agg0[idx] / c + g_rootx[idx];
    g_h[idx] = fmaxf(v, 0.f);
    g_agg1[idx] = 0.f;
}

// out[n] = sum_o relu(agg1[n,o]/max(cnt,1) + rootx[n,o]) * head_w[o] + head_b
__global__ void head_kernel(const float* __restrict__ hw,
                            const float* __restrict__ hb,
                            float* __restrict__ out) {
    int n = blockIdx.x * blockDim.x + threadIdx.x;
    if (n >= NN) return;
    float inv = 1.f / fmaxf(g_cnt[n], 1.f);
    const float* ag = g_agg1 + (size_t)n * 16;
    const float* rx = g_rootx + (size_t)n * 16;
    float s = hb[0];
#pragma unroll
    for (int o = 0; o < 16; o++) {
        float v = fmaxf(fmaf(ag[o], inv, rx[o]), 0.f);
        s = fmaf(v, hw[o], s);
    }
    out[n] = s;
}

// ---------------- launch ----------------
extern "C" void kernel_launch(void* const* d_in, const int* in_sizes, int n_in,
                              void* d_out, int out_size) {
    const float* x     = (const float*)d_in[0];
    const void*  ei    = d_in[1];
    const float* ea    = (const float*)d_in[2];
    const float* nn_w0 = (const float*)d_in[3];
    const float* nn_b0 = (const float*)d_in[4];
    const float* root0 = (const float*)d_in[5];
    const float* bias0 = (const float*)d_in[6];
    const float* nn_w1 = (const float*)d_in[7];
    const float* nn_b1 = (const float*)d_in[8];
    const float* root1 = (const float*)d_in[9];
    const float* bias1 = (const float*)d_in[10];
    const float* headw = (const float*)d_in[11];
    const float* headb = (const float*)d_in[12];
    float* out = (float*)d_out;

    const int TB = 256;
    const int EB = (EE * 8 + TB - 1) / TB;   // 8 lanes per edge

    zero_detect_kernel<<<1024, TB>>>(ei);
    node_prep_kernel<<<1184, TB>>>(x, nn_w0, nn_b0, root0, bias0);
    edge_kernel<<<EB, TB>>>(ei, ea, /*layer=*/0, /*do_cnt=*/1);
    relu_h_kernel<<<(NN * 16 + TB - 1) / TB, TB>>>();
    node_prep_kernel<<<1184, TB>>>(nullptr, nn_w1, nn_b1, root1, bias1);
    edge_kernel<<<EB, TB>>>(ei, ea, /*layer=*/1, /*do_cnt=*/0);
    head_kernel<<<(NN + TB - 1) / TB, TB>>>(headw, headb, out);
}

// round 11
// speedup vs baseline: 1.3917x; 1.0347x over previous
#include <cuda_runtime.h>
#include <cuda_fp16.h>

// Problem constants
#define NN    50000
#define EE    800000
#define ROW   160     // logical node-prep row in floats: [T 0..127 | xb 128..143 | rootx 144..159]
#define ROWH  128     // fp16 table stride in halves = 256 B = 2 x 128B lines.
                      // o-major permuted: slot s (16 slots x 8 halves), s<8 -> o=2s, s>=8 -> o=2(s-8)+1.

// ---------------- scratch (static device memory; no runtime allocation) ----------------
__device__ __half g_TextH[(size_t)NN * ROWH];   // 12.8 MB, fits L2 easily
__device__ float  g_xb[NN * 16];                // fp32 xb side table
__device__ float  g_rootx[NN * 16];
__device__ float  g_h[NN * 16];
__device__ float  g_agg0[NN * 16];
__device__ float  g_agg1[NN * 16];
__device__ float  g_cnt[NN];
__device__ int    g_is64;   // 1 if edge_index is int64, 0 if int32

// ---------------- helpers ----------------
__device__ __forceinline__ float4 f4fma(float s, float4 a, float4 b) {
    b.x = fmaf(s, a.x, b.x);
    b.y = fmaf(s, a.y, b.y);
    b.z = fmaf(s, a.z, b.z);
    b.w = fmaf(s, a.w, b.w);
    return b;
}

// vectorized no-return atomic add (sm_90+, PTX ISA 8.1)
__device__ __forceinline__ void red2(float* p, float a, float b) {
    asm volatile("red.global.add.v2.f32 [%0], {%1, %2};"
                 :: "l"(p), "f"(a), "f"(b) : "memory");
}

// ---------------- kernels ----------------

// Build per-node tables (2 nodes per thread). When do_zero != 0 this kernel
// also zeroes agg0/cnt (grid-stride, overlaps with the smem GEMM work) and
// block 0 / warp 0 probes the edge_index dtype.
//   j4 in [0,32):  T float4 (d=j4>>2, o=(j4&3)*4..+3) -> permuted fp16 slots
//   j4 in [32,36): xb  -> fp32 g_xb
//   j4 in [36,40): rootx -> fp32 g_rootx
__global__ void __launch_bounds__(256)
node_prep_kernel(const float* __restrict__ xin,   // nullptr -> use g_h
                 const float* __restrict__ nw,
                 const float* __restrict__ nb,
                 const float* __restrict__ rt,
                 const float* __restrict__ bs,
                 const void* __restrict__ ei,
                 int do_zero) {
    __shared__ float Wc[16 * ROW];
    __shared__ float Bc[ROW];
    const float* in = (xin != nullptr) ? xin : g_h;

    if (do_zero) {
        if (blockIdx.x == 0 && threadIdx.x < 32) {
            const unsigned long long* p = (const unsigned long long*)ei;
            int t = threadIdx.x;
            bool bad = (p[t] >= (unsigned long long)NN) ||
                       (p[t + 32] >= (unsigned long long)NN);
            unsigned m = __ballot_sync(0xffffffffu, bad);
            if (t == 0) g_is64 = (m == 0) ? 1 : 0;
        }
        int idx = blockIdx.x * blockDim.x + threadIdx.x;
        int stride = gridDim.x * blockDim.x;
        float4 z4 = make_float4(0.f, 0.f, 0.f, 0.f);
        for (int i = idx; i < NN * 4; i += stride)
            ((float4*)g_agg0)[i] = z4;
        for (int i = idx; i < NN; i += stride)
            g_cnt[i] = 0.f;
    }

    for (int t = threadIdx.x; t < 16 * ROW; t += blockDim.x) {
        int i = t / ROW, j = t % ROW;
        float w;
        if (j < 128) {
            int d = j >> 4, o = j & 15;
            w = nw[d * 256 + i * 16 + o];
        } else if (j < 144) {
            int o = j - 128;
            w = nb[i * 16 + o];
        } else {
            int o = j - 144;
            w = rt[i * 16 + o];
        }
        Wc[t] = w;
    }
    for (int t = threadIdx.x; t < ROW; t += blockDim.x)
        Bc[t] = (t >= 144) ? bs[t - 144] : 0.f;
    __syncthreads();

    const int total = (NN / 2) * (ROW / 4);  // one thread per float4 of 2 nodes
    for (int g = blockIdx.x * blockDim.x + threadIdx.x; g < total;
         g += gridDim.x * blockDim.x) {
        int pair = g / (ROW / 4);
        int j4 = g % (ROW / 4);
        int n0 = pair * 2;
        const float4* xr0 = (const float4*)(in + (size_t)n0 * 16);
        const float4* xr1 = (const float4*)(in + (size_t)(n0 + 1) * 16);
        float4 a0 = xr0[0], a1 = xr0[1], a2 = xr0[2], a3 = xr0[3];
        float4 b0 = xr1[0], b1 = xr1[1], b2 = xr1[2], b3 = xr1[3];
        float xv0[16] = {a0.x, a0.y, a0.z, a0.w, a1.x, a1.y, a1.z, a1.w,
                         a2.x, a2.y, a2.z, a2.w, a3.x, a3.y, a3.z, a3.w};
        float xv1[16] = {b0.x, b0.y, b0.z, b0.w, b1.x, b1.y, b1.z, b1.w,
                         b2.x, b2.y, b2.z, b2.w, b3.x, b3.y, b3.z, b3.w};
        float4 base = *(const float4*)&Bc[j4 * 4];
        float4 acc0 = base, acc1 = base;
#pragma unroll
        for (int i = 0; i < 16; i++) {
            float4 w = *(const float4*)&Wc[i * ROW + j4 * 4];
            acc0 = f4fma(xv0[i], w, acc0);
            acc1 = f4fma(xv1[i], w, acc1);
        }
        if (j4 < 32) {
            // Permuted slots: even o -> slot o/2; odd o -> slot 8+o/2.
            // base half index for (d=j4>>2, o0=(j4&3)*4): (j4&3)*16 + (j4>>2)
            int bi = (j4 & 3) * 16 + (j4 >> 2);
            __half* r0 = g_TextH + (size_t)n0 * ROWH;
            __half* r1 = g_TextH + (size_t)(n0 + 1) * ROWH;
            r0[bi]      = __float2half_rn(acc0.x);   // o0   (even)
            r0[bi + 64] = __float2half_rn(acc0.y);   // o0+1 (odd)
            r0[bi + 8]  = __float2half_rn(acc0.z);   // o0+2 (even)
            r0[bi + 72] = __float2half_rn(acc0.w);   // o0+3 (odd)
            r1[bi]      = __float2half_rn(acc1.x);
            r1[bi + 64] = __float2half_rn(acc1.y);
            r1[bi + 8]  = __float2half_rn(acc1.z);
            r1[bi + 72] = __float2half_rn(acc1.w);
        } else if (j4 < 36) {
            int o0 = (j4 - 32) * 4;
            *(float4*)&g_xb[n0 * 16 + o0] = acc0;
            *(float4*)&g_xb[(n0 + 1) * 16 + o0] = acc1;
        } else {
            int o0 = (j4 - 36) * 4;
            *(float4*)&g_rootx[n0 * 16 + o0] = acc0;
            *(float4*)&g_rootx[(n0 + 1) * 16 + o0] = acc1;
        }
    }
}

// 8 cooperative lanes per edge, shuffle-free fp16 o-major gather.
// Lane l: 16B load at row+16l      -> T[:, o=2l]   (8 halves, d0..7)
//         16B load at row+128+16l  -> T[:, o=2l+1]
// Each instruction covers exactly one 128B line per edge; one red.v2/lane.
__global__ void __launch_bounds__(256)
edge_kernel(const void* __restrict__ ei_raw,
            const float* __restrict__ ea,
            int layer, int do_cnt) {
    int gt = blockIdx.x * blockDim.x + threadIdx.x;
    int e = gt >> 3;               // grid exact: EE*8 == 25000*256
    int l = gt & 7;

    int src, dst;
    if (g_is64) {
        const long long* ei = (const long long*)ei_raw;
        src = (int)ei[e];
        dst = (int)ei[EE + e];
    } else {
        const int* ei = (const int*)ei_raw;
        src = ei[e];
        dst = ei[EE + e];
    }
    bool ok = ((unsigned)src < NN) && ((unsigned)dst < NN);
    if (!ok) src = 0;

    const float4* eap = (const float4*)(ea + (size_t)e * 8);
    float4 a0 = eap[0], a1 = eap[1];

    const char* row = (const char*)(g_TextH + (size_t)src * ROWH);
    float4 rA = *(const float4*)(row + 16 * l);        // T[:, 2l]
    float4 rB = *(const float4*)(row + 128 + 16 * l);  // T[:, 2l+1]

    float mA, mB;
    {
        float2 f0 = __half22float2(*(__half2*)&rA.x);  // d0,d1
        float2 f1 = __half22float2(*(__half2*)&rA.y);  // d2,d3
        float2 f2 = __half22float2(*(__half2*)&rA.z);  // d4,d5
        float2 f3 = __half22float2(*(__half2*)&rA.w);  // d6,d7
        mA = f0.x * a0.x;
        mA = fmaf(f0.y, a0.y, mA);
        mA = fmaf(f1.x, a0.z, mA);
        mA = fmaf(f1.y, a0.w, mA);
        mA = fmaf(f2.x, a1.x, mA);
        mA = fmaf(f2.y, a1.y, mA);
        mA = fmaf(f3.x, a1.z, mA);
        mA = fmaf(f3.y, a1.w, mA);
    }
    {
        float2 f0 = __half22float2(*(__half2*)&rB.x);
        float2 f1 = __half22float2(*(__half2*)&rB.y);
        float2 f2 = __half22float2(*(__half2*)&rB.z);
        float2 f3 = __half22float2(*(__half2*)&rB.w);
        mB = f0.x * a0.x;
        mB = fmaf(f0.y, a0.y, mB);
        mB = fmaf(f1.x, a0.z, mB);
        mB = fmaf(f1.y, a0.w, mB);
        mB = fmaf(f2.x, a1.x, mB);
        mB = fmaf(f2.y, a1.y, mB);
        mB = fmaf(f3.x, a1.z, mB);
        mB = fmaf(f3.y, a1.w, mB);
    }

    float2 xb2 = *(const float2*)(g_xb + (size_t)src * 16 + 2 * l);
    mA += xb2.x;
    mB += xb2.y;

    if (ok) {
        float* dstp = (layer ? g_agg1 : g_agg0) + (size_t)dst * 16 + 2 * l;
        red2(dstp, mA, mB);
        if (do_cnt && l == 0) atomicAdd(&g_cnt[dst], 1.0f);
    }
}

// Vectorized: one thread per float4. h = relu(agg0/max(cnt,1)+rootx);
// also zeroes agg1 for layer 1.
__global__ void relu_h_kernel() {
    int i = blockIdx.x * blockDim.x + threadIdx.x;
    if (i >= NN * 4) return;
    int n = i >> 2;
    float inv = 1.f / fmaxf(g_cnt[n], 1.f);
    float4 ag = ((const float4*)g_agg0)[i];
    float4 rx = ((const float4*)g_rootx)[i];
    float4 hv;
    hv.x = fmaxf(fmaf(ag.x, inv, rx.x), 0.f);
    hv.y = fmaxf(fmaf(ag.y, inv, rx.y), 0.f);
    hv.z = fmaxf(fmaf(ag.z, inv, rx.z), 0.f);
    hv.w = fmaxf(fmaf(ag.w, inv, rx.w), 0.f);
    ((float4*)g_h)[i] = hv;
    ((float4*)g_agg1)[i] = make_float4(0.f, 0.f, 0.f, 0.f);
}

// out[n] = sum_o relu(agg1[n,o]/max(cnt,1) + rootx[n,o]) * head_w[o] + head_b
__global__ void head_kernel(const float* __restrict__ hw,
                            const float* __restrict__ hb,
                            float* __restrict__ out) {
    int n = blockIdx.x * blockDim.x + threadIdx.x;
    if (n >= NN) return;
    float inv = 1.f / fmaxf(g_cnt[n], 1.f);
    const float4* ag = (const float4*)(g_agg1 + (size_t)n * 16);
    const float4* rx = (const float4*)(g_rootx + (size_t)n * 16);
    float s = hb[0];
#pragma unroll
    for (int q = 0; q < 4; q++) {
        float4 a = ag[q], r = rx[q];
        const float4 w = ((const float4*)hw)[q];
        s = fmaf(fmaxf(fmaf(a.x, inv, r.x), 0.f), w.x, s);
        s = fmaf(fmaxf(fmaf(a.y, inv, r.y), 0.f), w.y, s);
        s = fmaf(fmaxf(fmaf(a.z, inv, r.z), 0.f), w.z, s);
        s = fmaf(fmaxf(fmaf(a.w, inv, r.w), 0.f), w.w, s);
    }
    out[n] = s;
}

// ---------------- launch ----------------
extern "C" void kernel_launch(void* const* d_in, const int* in_sizes, int n_in,
                              void* d_out, int out_size) {
    const float* x     = (const float*)d_in[0];
    const void*  ei    = d_in[1];
    const float* ea    = (const float*)d_in[2];
    const float* nn_w0 = (const float*)d_in[3];
    const float* nn_b0 = (const float*)d_in[4];
    const float* root0 = (const float*)d_in[5];
    const float* bias0 = (const float*)d_in[6];
    const float* nn_w1 = (const float*)d_in[7];
    const float* nn_b1 = (const float*)d_in[8];
    const float* root1 = (const float*)d_in[9];
    const float* bias1 = (const float*)d_in[10];
    const float* headw = (const float*)d_in[11];
    const float* headb = (const float*)d_in[12];
    float* out = (float*)d_out;

    const int TB = 256;
    const int EB = (EE * 8 + TB - 1) / TB;   // 8 lanes per edge

    node_prep_kernel<<<1184, TB>>>(x, nn_w0, nn_b0, root0, bias0, ei, /*do_zero=*/1);
    edge_kernel<<<EB, TB>>>(ei, ea, /*layer=*/0, /*do_cnt=*/1);
    relu_h_kernel<<<(NN * 4 + TB - 1) / TB, TB>>>();
    node_prep_kernel<<<1184, TB>>>(nullptr, nn_w1, nn_b1, root1, bias1, ei, /*do_zero=*/0);
    edge_kernel<<<EB, TB>>>(ei, ea, /*layer=*/1, /*do_cnt=*/0);
    head_kernel<<<(NN + TB - 1) / TB, TB>>>(headw, headb, out);
}

// round 12
// speedup vs baseline: 1.7691x; 1.2712x over previous
#include <cuda_runtime.h>
#include <cuda_fp16.h>

// Problem constants
#define NN    50000
#define EE    800000
#define ROWH  128     // fp16 table stride in halves = 256 B = 2 x 128B lines.
                      // o-major permuted: half idx = slot*8 + d; even o -> slot o/2, odd o -> slot 8+o/2.
#define MT    3125    // m-tiles of 16 nodes (50000 = 3125*16 exactly)
#define WSTRIDE 168   // Wt smem stride in floats: bank = t4*8+g -> conflict-free B-frag loads
#define SSTRIDE 136   // staging row stride in halves (272B, 16B-aligned)

// ---------------- scratch (static device memory; no runtime allocation) ----------------
__device__ __half g_TextH[(size_t)NN * ROWH];   // 12.8 MB
__device__ float  g_xb[NN * 16];
__device__ float  g_rootx[NN * 16];
__device__ float  g_h[NN * 16];
__device__ float  g_agg0[NN * 16];
__device__ float  g_agg1[NN * 16];
__device__ float  g_cnt[NN];
__device__ int    g_is64;   // 1 if edge_index is int64, 0 if int32

// ---------------- helpers ----------------
__device__ __forceinline__ unsigned tf32_of(float f) {
    unsigned r;
    asm("cvt.rna.tf32.f32 %0, %1;" : "=r"(r) : "f"(f));
    return r;
}

__device__ __forceinline__ void mma_tf32(float& c0, float& c1, float& c2, float& c3,
                                         unsigned a0, unsigned a1, unsigned a2, unsigned a3,
                                         unsigned b0, unsigned b1) {
    asm("mma.sync.aligned.m16n8k8.row.col.f32.tf32.tf32.f32 "
        "{%0,%1,%2,%3},{%4,%5,%6,%7},{%8,%9},{%0,%1,%2,%3};"
        : "+f"(c0), "+f"(c1), "+f"(c2), "+f"(c3)
        : "r"(a0), "r"(a1), "r"(a2), "r"(a3), "r"(b0), "r"(b1));
}

// vectorized no-return atomic add (sm_90+, PTX ISA 8.1)
__device__ __forceinline__ void red2(float* p, float a, float b) {
    asm volatile("red.global.add.v2.f32 [%0], {%1, %2};"
                 :: "l"(p), "f"(a), "f"(b) : "memory");
}

// ---------------- kernels ----------------

// Tensor-core node prep: C[50000 x 160] = X[50000 x 16] * W[16 x 160] via
// mma.sync.m16n8k8.tf32. One warp per 16-node m-tile; 20 n-tiles; 2 k-steps.
// n-tiles 0..15 -> T (fp16, permuted layout, staged in smem then coalesced out),
// 16..17 -> xb (fp32), 18..19 -> rootx (fp32, +bias).
// When do_zero: also zeroes agg0/cnt and block0/warp0 probes edge_index dtype.
__global__ void __launch_bounds__(256)
node_prep_kernel(const float* __restrict__ xin,   // nullptr -> use g_h
                 const float* __restrict__ nw,
                 const float* __restrict__ nb,
                 const float* __restrict__ rt,
                 const float* __restrict__ bs,
                 const void* __restrict__ ei,
                 int do_zero) {
    __shared__ unsigned Wt[16 * WSTRIDE];           // tf32 weights, [k][j]
    __shared__ float    Bs[16];                     // bias
    __shared__ __half   stage[8][16 * SSTRIDE];     // per-warp T staging
    const float* in = (xin != nullptr) ? xin : g_h;

    if (do_zero) {
        if (blockIdx.x == 0 && threadIdx.x < 32) {
            const unsigned long long* p = (const unsigned long long*)ei;
            int t = threadIdx.x;
            bool bad = (p[t] >= (unsigned long long)NN) ||
                       (p[t + 32] >= (unsigned long long)NN);
            unsigned m = __ballot_sync(0xffffffffu, bad);
            if (t == 0) g_is64 = (m == 0) ? 1 : 0;
        }
        int idx = blockIdx.x * blockDim.x + threadIdx.x;
        int stride = gridDim.x * blockDim.x;
        float4 z4 = make_float4(0.f, 0.f, 0.f, 0.f);
        for (int i = idx; i < NN * 4; i += stride)
            ((float4*)g_agg0)[i] = z4;
        for (int i = idx; i < NN; i += stride)
            g_cnt[i] = 0.f;
    }

    // Stage weights as tf32: W[k=i][j], j<128: nn_w (d=j>>4,o=j&15); 128..143: nn_b; 144..159: root.
    for (int t = threadIdx.x; t < 16 * 160; t += blockDim.x) {
        int i = t / 160, j = t % 160;
        float w;
        if (j < 128) {
            int d = j >> 4, o = j & 15;
            w = nw[d * 256 + i * 16 + o];
        } else if (j < 144) {
            w = nb[i * 16 + (j - 128)];
        } else {
            w = rt[i * 16 + (j - 144)];
        }
        Wt[i * WSTRIDE + j] = tf32_of(w);
    }
    if (threadIdx.x < 16) Bs[threadIdx.x] = bs[threadIdx.x];
    __syncthreads();

    int wid = threadIdx.x >> 5;
    int lane = threadIdx.x & 31;
    int g = lane >> 2;          // group id 0..7
    int t4 = lane & 3;          // thread-in-group

    int m = blockIdx.x * 8 + wid;
    if (m >= MT) return;
    int base = m * 16;

    // A fragments (rows base+g, base+g+8; k = kh*8 + t4, +4)
    unsigned A[2][4];
    const float* x0 = in + (size_t)(base + g) * 16;
    const float* x1 = in + (size_t)(base + g + 8) * 16;
#pragma unroll
    for (int kh = 0; kh < 2; kh++) {
        A[kh][0] = tf32_of(x0[kh * 8 + t4]);
        A[kh][1] = tf32_of(x1[kh * 8 + t4]);
        A[kh][2] = tf32_of(x0[kh * 8 + t4 + 4]);
        A[kh][3] = tf32_of(x1[kh * 8 + t4 + 4]);
    }

    __half* st = stage[wid];

#pragma unroll
    for (int nbt = 0; nbt < 20; nbt++) {
        float c0 = 0.f, c1 = 0.f, c2 = 0.f, c3 = 0.f;
#pragma unroll
        for (int kh = 0; kh < 2; kh++) {
            unsigned b0 = Wt[(kh * 8 + t4) * WSTRIDE + nbt * 8 + g];
            unsigned b1 = Wt[(kh * 8 + t4 + 4) * WSTRIDE + nbt * 8 + g];
            mma_tf32(c0, c1, c2, c3, A[kh][0], A[kh][1], A[kh][2], A[kh][3], b0, b1);
        }
        // C layout: c0=(row g, col 2*t4), c1=(g, 2*t4+1), c2=(g+8, 2*t4), c3=(g+8, 2*t4+1)
        if (nbt < 16) {
            int d = nbt >> 1;                 // j>>4 constant within tile
            int o0 = (nbt & 1) * 8 + 2 * t4;  // even column
            int idx0 = (o0 >> 1) * 8 + d;     // even col slot; odd col = +64
            st[g * SSTRIDE + idx0]            = __float2half_rn(c0);
            st[g * SSTRIDE + idx0 + 64]       = __float2half_rn(c1);
            st[(g + 8) * SSTRIDE + idx0]      = __float2half_rn(c2);
            st[(g + 8) * SSTRIDE + idx0 + 64] = __float2half_rn(c3);
        } else if (nbt < 18) {
            int o0 = (nbt - 16) * 8 + 2 * t4;
            *(float2*)&g_xb[(size_t)(base + g) * 16 + o0]     = make_float2(c0, c1);
            *(float2*)&g_xb[(size_t)(base + g + 8) * 16 + o0] = make_float2(c2, c3);
        } else {
            int o0 = (nbt - 18) * 8 + 2 * t4;
            float b0v = Bs[o0], b1v = Bs[o0 + 1];
            *(float2*)&g_rootx[(size_t)(base + g) * 16 + o0]     = make_float2(c0 + b0v, c1 + b1v);
            *(float2*)&g_rootx[(size_t)(base + g + 8) * 16 + o0] = make_float2(c2 + b0v, c3 + b1v);
        }
    }
    __syncwarp();

    // Coalesced copy: staging rows (SSTRIDE halves) -> g_TextH rows (128 halves).
    for (int it = lane; it < 256; it += 32) {
        int r = it >> 4;          // node row 0..15
        int q = it & 15;          // float4 (8 halves) within row
        float4 v = *(const float4*)(st + r * SSTRIDE + q * 8);
        *(float4*)((char*)(g_TextH + (size_t)(base + r) * ROWH) + q * 16) = v;
    }
}

// 8 cooperative lanes per edge, shuffle-free fp16 o-major gather.
// Lane l: 16B load at row+16l      -> T[:, o=2l]   (8 halves, d0..7)
//         16B load at row+128+16l  -> T[:, o=2l+1]
// Each instruction covers exactly one 128B line per edge; one red.v2/lane.
__global__ void __launch_bounds__(256)
edge_kernel(const void* __restrict__ ei_raw,
            const float* __restrict__ ea,
            int layer, int do_cnt) {
    int gt = blockIdx.x * blockDim.x + threadIdx.x;
    int e = gt >> 3;               // grid exact: EE*8 == 25000*256
    int l = gt & 7;

    int src, dst;
    if (g_is64) {
        const long long* ei = (const long long*)ei_raw;
        src = (int)ei[e];
        dst = (int)ei[EE + e];
    } else {
        const int* ei = (const int*)ei_raw;
        src = ei[e];
        dst = ei[EE + e];
    }
    bool ok = ((unsigned)src < NN) && ((unsigned)dst < NN);
    if (!ok) src = 0;

    const float4* eap = (const float4*)(ea + (size_t)e * 8);
    float4 a0 = eap[0], a1 = eap[1];

    const char* row = (const char*)(g_TextH + (size_t)src * ROWH);
    float4 rA = *(const float4*)(row + 16 * l);        // T[:, 2l]
    float4 rB = *(const float4*)(row + 128 + 16 * l);  // T[:, 2l+1]

    float mA, mB;
    {
        float2 f0 = __half22float2(*(__half2*)&rA.x);  // d0,d1
        float2 f1 = __half22float2(*(__half2*)&rA.y);  // d2,d3
        float2 f2 = __half22float2(*(__half2*)&rA.z);  // d4,d5
        float2 f3 = __half22float2(*(__half2*)&rA.w);  // d6,d7
        mA = f0.x * a0.x;
        mA = fmaf(f0.y, a0.y, mA);
        mA = fmaf(f1.x, a0.z, mA);
        mA = fmaf(f1.y, a0.w, mA);
        mA = fmaf(f2.x, a1.x, mA);
        mA = fmaf(f2.y, a1.y, mA);
        mA = fmaf(f3.x, a1.z, mA);
        mA = fmaf(f3.y, a1.w, mA);
    }
    {
        float2 f0 = __half22float2(*(__half2*)&rB.x);
        float2 f1 = __half22float2(*(__half2*)&rB.y);
        float2 f2 = __half22float2(*(__half2*)&rB.z);
        float2 f3 = __half22float2(*(__half2*)&rB.w);
        mB = f0.x * a0.x;
        mB = fmaf(f0.y, a0.y, mB);
        mB = fmaf(f1.x, a0.z, mB);
        mB = fmaf(f1.y, a0.w, mB);
        mB = fmaf(f2.x, a1.x, mB);
        mB = fmaf(f2.y, a1.y, mB);
        mB = fmaf(f3.x, a1.z, mB);
        mB = fmaf(f3.y, a1.w, mB);
    }

    float2 xb2 = *(const float2*)(g_xb + (size_t)src * 16 + 2 * l);
    mA += xb2.x;
    mB += xb2.y;

    if (ok) {
        float* dstp = (layer ? g_agg1 : g_agg0) + (size_t)dst * 16 + 2 * l;
        red2(dstp, mA, mB);
        if (do_cnt && l == 0) atomicAdd(&g_cnt[dst], 1.0f);
    }
}

// Vectorized: one thread per float4. h = relu(agg0/max(cnt,1)+rootx);
// also zeroes agg1 for layer 1.
__global__ void relu_h_kernel() {
    int i = blockIdx.x * blockDim.x + threadIdx.x;
    if (i >= NN * 4) return;
    int n = i >> 2;
    float inv = 1.f / fmaxf(g_cnt[n], 1.f);
    float4 ag = ((const float4*)g_agg0)[i];
    float4 rx = ((const float4*)g_rootx)[i];
    float4 hv;
    hv.x = fmaxf(fmaf(ag.x, inv, rx.x), 0.f);
    hv.y = fmaxf(fmaf(ag.y, inv, rx.y), 0.f);
    hv.z = fmaxf(fmaf(ag.z, inv, rx.z), 0.f);
    hv.w = fmaxf(fmaf(ag.w, inv, rx.w), 0.f);
    ((float4*)g_h)[i] = hv;
    ((float4*)g_agg1)[i] = make_float4(0.f, 0.f, 0.f, 0.f);
}

// out[n] = sum_o relu(agg1[n,o]/max(cnt,1) + rootx[n,o]) * head_w[o] + head_b
__global__ void head_kernel(const float* __restrict__ hw,
                            const float* __restrict__ hb,
                            float* __restrict__ out) {
    int n = blockIdx.x * blockDim.x + threadIdx.x;
    if (n >= NN) return;
    float inv = 1.f / fmaxf(g_cnt[n], 1.f);
    const float4* ag = (const float4*)(g_agg1 + (size_t)n * 16);
    const float4* rx = (const float4*)(g_rootx + (size_t)n * 16);
    float s = hb[0];
#pragma unroll
    for (int q = 0; q < 4; q++) {
        float4 a = ag[q], r = rx[q];
        const float4 w = ((const float4*)hw)[q];
        s = fmaf(fmaxf(fmaf(a.x, inv, r.x), 0.f), w.x, s);
        s = fmaf(fmaxf(fmaf(a.y, inv, r.y), 0.f), w.y, s);
        s = fmaf(fmaxf(fmaf(a.z, inv, r.z), 0.f), w.z, s);
        s = fmaf(fmaxf(fmaf(a.w, inv, r.w), 0.f), w.w, s);
    }
    out[n] = s;
}

// ---------------- launch ----------------
extern "C" void kernel_launch(void* const* d_in, const int* in_sizes, int n_in,
                              void* d_out, int out_size) {
    const float* x     = (const float*)d_in[0];
    const void*  ei    = d_in[1];
    const float* ea    = (const float*)d_in[2];
    const float* nn_w0 = (const float*)d_in[3];
    const float* nn_b0 = (const float*)d_in[4];
    const float* root0 = (const float*)d_in[5];
    const float* bias0 = (const float*)d_in[6];
    const float* nn_w1 = (const float*)d_in[7];
    const float* nn_b1 = (const float*)d_in[8];
    const float* root1 = (const float*)d_in[9];
    const float* bias1 = (const float*)d_in[10];
    const float* headw = (const float*)d_in[11];
    const float* headb = (const float*)d_in[12];
    float* out = (float*)d_out;

    const int TB = 256;
    const int EB = (EE * 8 + TB - 1) / TB;   // 8 lanes per edge
    const int PB = (MT + 7) / 8;             // 1 warp per m-tile, 8 warps/block

    node_prep_kernel<<<PB, TB>>>(x, nn_w0, nn_b0, root0, bias0, ei, /*do_zero=*/1);
    edge_kernel<<<EB, TB>>>(ei, ea, /*layer=*/0, /*do_cnt=*/1);
    relu_h_kernel<<<(NN * 4 + TB - 1) / TB, TB>>>();
    node_prep_kernel<<<PB, TB>>>(nullptr, nn_w1, nn_b1, root1, bias1, ei, /*do_zero=*/0);
    edge_kernel<<<EB, TB>>>(ei, ea, /*layer=*/1, /*do_cnt=*/0);
    head_kernel<<<(NN + TB - 1) / TB, TB>>>(headw, headb, out);
}